// round 1
// baseline (speedup 1.0000x reference)
#include <cuda_runtime.h>
#include <cuda_bf16.h>
#include <math.h>

#define TT 4096
#define DD 1024
#define NH 16
#define HDIM 64

// Scratch (allocation-free rule: device globals)
__device__ float g_qkv[(size_t)TT * 3 * DD];   // 48 MB: per-row [q(1024) | k(1024) | v(1024)]
__device__ float g_att[(size_t)TT * DD];       // 16 MB: attention output, (T, H*HD) layout

__device__ __forceinline__ float fast_exp2(float x) {
    float y;
    asm("ex2.approx.ftz.f32 %0, %1;" : "=f"(y) : "f"(x));
    return y;
}

// ---------------------------------------------------------------------------
// C[M,N] = A[M,K] @ B[K,N], all row-major. Requires M%128==0, N%128==0, K%8==0.
// 128x128 block tile, BK=8, 8x8 per-thread tile, 256 threads.
// ---------------------------------------------------------------------------
__global__ __launch_bounds__(256) void sgemm_kernel(
    const float* __restrict__ A, const float* __restrict__ B,
    float* __restrict__ C, int M, int N, int K)
{
    const int BK = 8;
    __shared__ float As[BK][128];   // transposed A tile: As[k][m]
    __shared__ float Bs[BK][128];

    const int tid = threadIdx.x;
    const int bm = blockIdx.y * 128;
    const int bn = blockIdx.x * 128;
    const int tr = (tid / 16) * 8;
    const int tc = (tid % 16) * 8;

    const int arow = tid >> 1;
    const int acol = (tid & 1) * 4;
    const int brow = tid >> 5;
    const int bcol = (tid & 31) * 4;

    float acc[8][8];
    #pragma unroll
    for (int i = 0; i < 8; i++)
        #pragma unroll
        for (int j = 0; j < 8; j++) acc[i][j] = 0.f;

    const float* Aptr = A + (size_t)(bm + arow) * K + acol;
    const float* Bptr = B + (size_t)brow * N + bn + bcol;

    for (int k0 = 0; k0 < K; k0 += BK) {
        float4 av = *(const float4*)(Aptr + k0);
        float4 bv = *(const float4*)(Bptr + (size_t)k0 * N);
        As[acol + 0][arow] = av.x;
        As[acol + 1][arow] = av.y;
        As[acol + 2][arow] = av.z;
        As[acol + 3][arow] = av.w;
        *(float4*)&Bs[brow][bcol] = bv;
        __syncthreads();

        #pragma unroll
        for (int k = 0; k < BK; k++) {
            float ra[8], rb[8];
            #pragma unroll
            for (int i = 0; i < 8; i++) ra[i] = As[k][tr + i];
            #pragma unroll
            for (int j = 0; j < 8; j++) rb[j] = Bs[k][tc + j];
            #pragma unroll
            for (int i = 0; i < 8; i++)
                #pragma unroll
                for (int j = 0; j < 8; j++)
                    acc[i][j] = fmaf(ra[i], rb[j], acc[i][j]);
        }
        __syncthreads();
    }

    #pragma unroll
    for (int i = 0; i < 8; i++) {
        float* cp = C + (size_t)(bm + tr + i) * N + bn + tc;
        *(float4*)(cp)     = make_float4(acc[i][0], acc[i][1], acc[i][2], acc[i][3]);
        *(float4*)(cp + 4) = make_float4(acc[i][4], acc[i][5], acc[i][6], acc[i][7]);
    }
}

// ---------------------------------------------------------------------------
// Causal flash attention, fp32. One block = 128 consecutive queries of one head.
// Thread-per-query; q[64] + acc[64] in registers; K/V tiles (64 keys) in shared,
// read as broadcast (all threads touch the same element simultaneously).
// Online softmax with per-16-key-chunk max/rescale in log2 domain.
// ---------------------------------------------------------------------------
__global__ __launch_bounds__(128) void attn_kernel(
    const float* __restrict__ qkv, float* __restrict__ out)
{
    const int h  = blockIdx.y;
    const int q0 = blockIdx.x * 128;
    const int r  = q0 + threadIdx.x;          // this thread's query row

    __shared__ float Ks[64][HDIM];
    __shared__ float Vs[64][HDIM];

    // q scaled by (1/sqrt(HD)) * log2(e) so scores are already in log2 units
    const float sc = 0.125f * 1.4426950408889634f;
    float q[HDIM];
    const float* qp = qkv + (size_t)r * (3 * DD) + h * HDIM;
    #pragma unroll
    for (int d4 = 0; d4 < HDIM / 4; d4++) {
        float4 v = *(const float4*)(qp + d4 * 4);
        q[d4 * 4 + 0] = v.x * sc;
        q[d4 * 4 + 1] = v.y * sc;
        q[d4 * 4 + 2] = v.z * sc;
        q[d4 * 4 + 3] = v.w * sc;
    }

    float m = -INFINITY, l = 0.f;
    float acc[HDIM];
    #pragma unroll
    for (int d = 0; d < HDIM; d++) acc[d] = 0.f;

    const int kend = q0 + 128;                // causal: keys [0, kend) cover all threads

    for (int k0 = 0; k0 < kend; k0 += 64) {
        // cooperative tile load: 64 keys x 64 dims of K and V (float4, coalesced-ish)
        for (int i = threadIdx.x; i < 64 * 16; i += 128) {
            int row = i >> 4;
            int c4  = (i & 15) * 4;
            const float* kp = qkv + (size_t)(k0 + row) * (3 * DD) + DD + h * HDIM + c4;
            *(float4*)&Ks[row][c4] = *(const float4*)kp;
            *(float4*)&Vs[row][c4] = *(const float4*)(kp + DD);
        }
        __syncthreads();

        #pragma unroll
        for (int jc = 0; jc < 64; jc += 16) {
            float s[16];
            float cmax = m;
            #pragma unroll
            for (int jj = 0; jj < 16; jj++) {
                const int key = k0 + jc + jj;
                float sj = 0.f;
                const float4* kr = (const float4*)(&Ks[jc + jj][0]);
                #pragma unroll
                for (int d4 = 0; d4 < HDIM / 4; d4++) {
                    float4 kv = kr[d4];
                    sj = fmaf(q[d4 * 4 + 0], kv.x, sj);
                    sj = fmaf(q[d4 * 4 + 1], kv.y, sj);
                    sj = fmaf(q[d4 * 4 + 2], kv.z, sj);
                    sj = fmaf(q[d4 * 4 + 3], kv.w, sj);
                }
                sj = (key <= r) ? sj : -INFINITY;
                s[jj] = sj;
                cmax = fmaxf(cmax, sj);
            }
            // rescale (cmax >= m; first chunk of first tile always has a valid key,
            // so m is finite from then on and cmax-m is never NaN)
            float c = fast_exp2(m - cmax);
            m = cmax;
            l *= c;
            #pragma unroll
            for (int d = 0; d < HDIM; d++) acc[d] *= c;
            #pragma unroll
            for (int jj = 0; jj < 16; jj++) {
                float p = fast_exp2(s[jj] - m);   // masked keys: exp2(-inf)=0
                l += p;
                const float4* vr = (const float4*)(&Vs[jc + jj][0]);
                #pragma unroll
                for (int d4 = 0; d4 < HDIM / 4; d4++) {
                    float4 vv = vr[d4];
                    acc[d4 * 4 + 0] = fmaf(p, vv.x, acc[d4 * 4 + 0]);
                    acc[d4 * 4 + 1] = fmaf(p, vv.y, acc[d4 * 4 + 1]);
                    acc[d4 * 4 + 2] = fmaf(p, vv.z, acc[d4 * 4 + 2]);
                    acc[d4 * 4 + 3] = fmaf(p, vv.w, acc[d4 * 4 + 3]);
                }
            }
        }
        __syncthreads();
    }

    const float inv_l = 1.0f / l;
    float* op = out + (size_t)r * DD + h * HDIM;
    #pragma unroll
    for (int d4 = 0; d4 < HDIM / 4; d4++) {
        float4 v;
        v.x = acc[d4 * 4 + 0] * inv_l;
        v.y = acc[d4 * 4 + 1] * inv_l;
        v.z = acc[d4 * 4 + 2] * inv_l;
        v.w = acc[d4 * 4 + 3] * inv_l;
        *(float4*)(op + d4 * 4) = v;
    }
}

// ---------------------------------------------------------------------------
extern "C" void kernel_launch(void* const* d_in, const int* in_sizes, int n_in,
                              void* d_out, int out_size)
{
    const float* x    = (const float*)d_in[0];
    const float* wqkv = (const float*)d_in[1];
    const float* wout = (const float*)d_in[2];
    float* out = (float*)d_out;

    float* qkv = nullptr;
    float* att = nullptr;
    cudaGetSymbolAddress((void**)&qkv, g_qkv);
    cudaGetSymbolAddress((void**)&att, g_att);

    // 1) QKV projection: (4096x1024) @ (1024x3072)
    dim3 g1(3 * DD / 128, TT / 128);
    sgemm_kernel<<<g1, 256>>>(x, wqkv, qkv, TT, 3 * DD, DD);

    // 2) causal attention per head
    dim3 g2(TT / 128, NH);
    attn_kernel<<<g2, 128>>>(qkv, att);

    // 3) output projection: (4096x1024) @ (1024x1024)
    dim3 g3(DD / 128, TT / 128);
    sgemm_kernel<<<g3, 256>>>(att, wout, out, TT, DD, DD);
}